// round 1
// baseline (speedup 1.0000x reference)
#include <cuda_runtime.h>
#include <cuda_bf16.h>
#include <cstdint>

// Problem constants (fixed by the reference)
#define NQ      256      // number of queries (D)
#define KDIM    256      // descriptor dim (C)
#define DBP     257      // places_db row pitch in floats (256 dims + id)
#define NT      64       // db rows per tile
#define THREADS 256
#define APITCH  264      // padded bf16 row pitch for A in smem (conflict-free)
#define BPITCH  264
#define MAXH    1024
#define MIN_SIM_F 0.8f
#define TOPK    10
#define GRID_SMS 152

// Scratch (device globals — no allocations allowed)
__device__ int   g_hitCnt[NQ];
__device__ float g_hitSim[NQ * MAXH];
__device__ int   g_hitIdx[NQ * MAXH];

__global__ void init_kernel() {
    if (threadIdx.x < NQ) g_hitCnt[threadIdx.x] = 0;
}

// ---------------------------------------------------------------------------
// Fused convert + bf16 tensor-core GEMM + threshold scan.
// C[256, N] = desc[256,256] @ X[N,256]^T, emit (m, n, sim) for sim >= 0.8.
// ---------------------------------------------------------------------------
__global__ void __launch_bounds__(THREADS, 1)
gemm_scan_kernel(const float* __restrict__ desc,
                 const float* __restrict__ db,
                 int ndb, int ntiles)
{
    extern __shared__ __align__(16) unsigned char smem_raw[];
    __nv_bfloat16* As = reinterpret_cast<__nv_bfloat16*>(smem_raw);          // [NQ][APITCH]
    __nv_bfloat16* Bs = As + NQ * APITCH;                                    // [NT][BPITCH]

    const int tid  = threadIdx.x;
    const int lane = tid & 31;
    const int warp = tid >> 5;
    const int wm   = warp & 3;   // M group: rows [wm*64, wm*64+64)
    const int wn   = warp >> 2;  // N group: cols [wn*32, wn*32+32)

    // ---- Convert A (descriptors, f32 -> bf16 smem) once per CTA ----
    {
        const float4* A4 = reinterpret_cast<const float4*>(desc);
        #pragma unroll 4
        for (int i = tid; i < (NQ * KDIM) / 4; i += THREADS) {
            float4 v = A4[i];
            int e = i * 4;
            int r = e >> 8;       // /256
            int c = e & 255;
            __nv_bfloat162* p = reinterpret_cast<__nv_bfloat162*>(As + r * APITCH + c);
            p[0] = __floats2bfloat162_rn(v.x, v.y);
            p[1] = __floats2bfloat162_rn(v.z, v.w);
        }
    }

    // ---- Software-pipelined main loop over db tiles ----
    float4 st[17];  // register staging: 64*257 floats / 256 threads = 16.0625 f4
    int t = blockIdx.x;
    if (t < ntiles) {
        const float4* B4 = reinterpret_cast<const float4*>(db + (size_t)t * (NT * DBP));
        int nf4 = (min(NT, ndb - t * NT) * DBP) >> 2;
        #pragma unroll
        for (int it = 0; it < 17; it++) {
            int i = tid + it * THREADS;
            st[it] = (i < nf4) ? B4[i] : make_float4(0.f, 0.f, 0.f, 0.f);
        }
    }

    for (; t < ntiles; t += gridDim.x) {
        __syncthreads();  // previous tile's compute done; A-convert done (first iter)

        // st (tile t) -> Bs (bf16), handling the 257-float row pitch
        #pragma unroll
        for (int it = 0; it < 17; it++) {
            int i = tid + it * THREADS;
            if (i < (NT * DBP) / 4) {
                int e = i * 4;
                int r = e / DBP;
                int c = e - r * DBP;
                float v[4] = { st[it].x, st[it].y, st[it].z, st[it].w };
                #pragma unroll
                for (int j = 0; j < 4; j++) {
                    int cj = c + j, rj = r;
                    if (cj >= DBP) { cj -= DBP; rj++; }
                    if (cj < KDIM && rj < NT)
                        Bs[rj * BPITCH + cj] = __float2bfloat16(v[j]);
                }
            }
        }
        __syncthreads();

        // Issue gmem loads for the NEXT tile before computing (overlap with MMA)
        int nxt = t + gridDim.x;
        if (nxt < ntiles) {
            const float4* B4 = reinterpret_cast<const float4*>(db + (size_t)nxt * (NT * DBP));
            int nf4 = (min(NT, ndb - nxt * NT) * DBP) >> 2;
            #pragma unroll
            for (int it = 0; it < 17; it++) {
                int i = tid + it * THREADS;
                st[it] = (i < nf4) ? B4[i] : make_float4(0.f, 0.f, 0.f, 0.f);
            }
        }

        // ---- MMA compute: warp tile 64(M) x 32(N), K=256 ----
        float acc[4][4][4];
        #pragma unroll
        for (int mi = 0; mi < 4; mi++)
            #pragma unroll
            for (int ni = 0; ni < 4; ni++)
                #pragma unroll
                for (int cc = 0; cc < 4; cc++) acc[mi][ni][cc] = 0.f;

        const __nv_bfloat16* Ab = As + (wm * 64 + (lane >> 2)) * APITCH + (lane & 3) * 2;
        const __nv_bfloat16* Bb = Bs + (wn * 32 + (lane >> 2)) * BPITCH + (lane & 3) * 2;

        #pragma unroll
        for (int ks = 0; ks < 16; ks++) {
            const int k0 = ks * 16;
            uint32_t a[4][4], b[4][2];
            #pragma unroll
            for (int mi = 0; mi < 4; mi++) {
                const __nv_bfloat16* p = Ab + mi * 16 * APITCH + k0;
                a[mi][0] = *reinterpret_cast<const uint32_t*>(p);
                a[mi][1] = *reinterpret_cast<const uint32_t*>(p + 8 * APITCH);
                a[mi][2] = *reinterpret_cast<const uint32_t*>(p + 8);
                a[mi][3] = *reinterpret_cast<const uint32_t*>(p + 8 * APITCH + 8);
            }
            #pragma unroll
            for (int ni = 0; ni < 4; ni++) {
                const __nv_bfloat16* p = Bb + ni * 8 * BPITCH + k0;
                b[ni][0] = *reinterpret_cast<const uint32_t*>(p);
                b[ni][1] = *reinterpret_cast<const uint32_t*>(p + 8);
            }
            #pragma unroll
            for (int mi = 0; mi < 4; mi++)
                #pragma unroll
                for (int ni = 0; ni < 4; ni++)
                    asm volatile(
                        "mma.sync.aligned.m16n8k16.row.col.f32.bf16.bf16.f32 "
                        "{%0,%1,%2,%3}, {%4,%5,%6,%7}, {%8,%9}, {%0,%1,%2,%3};\n"
                        : "+f"(acc[mi][ni][0]), "+f"(acc[mi][ni][1]),
                          "+f"(acc[mi][ni][2]), "+f"(acc[mi][ni][3])
                        : "r"(a[mi][0]), "r"(a[mi][1]), "r"(a[mi][2]), "r"(a[mi][3]),
                          "r"(b[ni][0]), "r"(b[ni][1]));
        }

        // ---- Epilogue: fast max-tree, rare atomic append of hits ----
        float vmax = -1e30f;
        #pragma unroll
        for (int mi = 0; mi < 4; mi++)
            #pragma unroll
            for (int ni = 0; ni < 4; ni++)
                #pragma unroll
                for (int cc = 0; cc < 4; cc++) vmax = fmaxf(vmax, acc[mi][ni][cc]);

        if (vmax >= MIN_SIM_F) {
            const int row0 = t * NT;
            #pragma unroll
            for (int mi = 0; mi < 4; mi++)
                #pragma unroll
                for (int ni = 0; ni < 4; ni++)
                    #pragma unroll
                    for (int cc = 0; cc < 4; cc++) {
                        float v = acc[mi][ni][cc];
                        if (v >= MIN_SIM_F) {
                            int m = wm * 64 + mi * 16 + (lane >> 2) + ((cc >> 1) << 3);
                            int n = row0 + wn * 32 + ni * 8 + ((lane & 3) << 1) + (cc & 1);
                            if (n < ndb) {
                                int pos = atomicAdd(&g_hitCnt[m], 1);
                                if (pos < MAXH) {
                                    g_hitSim[m * MAXH + pos] = v;
                                    g_hitIdx[m * MAXH + pos] = n;
                                }
                            }
                        }
                    }
        }
    }
}

// ---------------------------------------------------------------------------
// Finalize: per-query top-10 (value desc, index asc), voting, box removal,
// sim_scores, output assembly. Single CTA of 256 threads.
// ---------------------------------------------------------------------------
__global__ void finalize_kernel(const float* __restrict__ boxes,
                                const float* __restrict__ db,
                                float* __restrict__ out)
{
    const int d = threadIdx.x;  // one thread per query / box
    __shared__ float sx1[NQ], sy1[NQ], sx2[NQ], sy2[NQ], sarea[NQ];
    __shared__ int   slbl[NQ];

    // --- top-10 among hits (sim desc, db-index asc == jax top_k tie order) ---
    float ts[TOPK];
    int   tn[TOPK];
    int cnt = g_hitCnt[d];
    if (cnt > MAXH) cnt = MAXH;
    int K = 0;
    for (int i = 0; i < cnt; i++) {
        float s = g_hitSim[d * MAXH + i];
        int   n = g_hitIdx[d * MAXH + i];
        int p = K;
        while (p > 0 && (s > ts[p - 1] || (s == ts[p - 1] && n < tn[p - 1]))) p--;
        if (p < TOPK) {
            int end = (K < TOPK) ? K : (TOPK - 1);
            for (int q = end; q > p; q--) { ts[q] = ts[q - 1]; tn[q] = tn[q - 1]; }
            ts[p] = s; tn[p] = n;
            if (K < TOPK) K++;
        }
    }

    // --- voting: max count; ties -> smallest class id (argmax over one-hot) ---
    int ids[TOPK];
    for (int k = 0; k < K; k++)
        ids[k] = (int)db[(size_t)tn[k] * DBP + (DBP - 1)];
    int best_cnt = 0, best_id = 0x7fffffff;
    for (int k = 0; k < K; k++) {
        int c = 0;
        for (int j = 0; j < K; j++) c += (ids[j] == ids[k]);
        if (c > best_cnt || (c == best_cnt && ids[k] < best_id)) {
            best_cnt = c; best_id = ids[k];
        }
    }
    int label = (best_cnt > 0) ? best_id : -1;

    // --- box overlap removal ---
    float x1 = boxes[d * 4 + 0], y1 = boxes[d * 4 + 1];
    float x2 = boxes[d * 4 + 2], y2 = boxes[d * 4 + 3];
    float area = (x2 - x1) * (y2 - y1);
    sx1[d] = x1; sy1[d] = y1; sx2[d] = x2; sy2[d] = y2;
    sarea[d] = area; slbl[d] = label;
    __syncthreads();

    bool removed = false;
    if (label >= 0) {
        for (int j = 0; j < NQ; j++) {
            if (j == d || slbl[j] != label) continue;
            float ix1 = fmaxf(x1, sx1[j]);
            float iy1 = fmaxf(y1, sy1[j]);
            float ix2 = fminf(x2, sx2[j]);
            float iy2 = fminf(y2, sy2[j]);
            float inter = fmaxf(ix2 - ix1, 0.f) * fmaxf(iy2 - iy1, 0.f);
            float asmall = fminf(area, sarea[j]);
            float ov = (asmall > 0.f) ? (inter / asmall) : 0.f;
            // remove[d] <=> exists same-label overlapping j with area_j <= area_d
            if (ov >= 0.8f && sarea[j] <= area) removed = true;
        }
    }
    int result = removed ? -1 : label;

    // --- sim_scores ---
    float score = 0.f;
    for (int k = 0; k < K; k++)
        if (ids[k] == result) score = fmaxf(score, ts[k]);

    // --- output: [final_boxes (1024)] [sim_scores (256)] [results (256)] ---
    for (int i = d; i < NQ * 4; i += NQ) out[i] = boxes[i];
    out[NQ * 4 + d]       = score;
    out[NQ * 5 + d]       = (float)result;
}

// ---------------------------------------------------------------------------
extern "C" void kernel_launch(void* const* d_in, const int* in_sizes, int n_in,
                              void* d_out, int out_size)
{
    // Identify inputs by size (order: final_boxes, descriptors, places_db)
    const float* boxes = (const float*)d_in[0];
    const float* desc  = (const float*)d_in[1];
    const float* db    = (const float*)d_in[2];
    int db_elems = in_sizes[2];
    for (int i = 0; i < n_in; i++) {
        if (in_sizes[i] == NQ * 4)            boxes = (const float*)d_in[i];
        else if (in_sizes[i] == NQ * KDIM)    desc  = (const float*)d_in[i];
        else                                  { db = (const float*)d_in[i]; db_elems = in_sizes[i]; }
    }
    int ndb    = db_elems / DBP;
    int ntiles = (ndb + NT - 1) / NT;

    const int smem_bytes = (NQ * APITCH + NT * BPITCH) * (int)sizeof(__nv_bfloat16);
    cudaFuncSetAttribute(gemm_scan_kernel,
                         cudaFuncAttributeMaxDynamicSharedMemorySize, smem_bytes);

    init_kernel<<<1, THREADS>>>();
    gemm_scan_kernel<<<GRID_SMS, THREADS, smem_bytes>>>(desc, db, ndb, ntiles);
    finalize_kernel<<<1, NQ>>>(boxes, db, (float*)d_out);
    (void)out_size;
}